// round 17
// baseline (speedup 1.0000x reference)
#include <cuda_runtime.h>
#include <cuda_fp16.h>
#include <math.h>
#include <stdint.h>

#define N      8192
#define INCH   256
#define OUTCH  64
#define NSPLIT 16
#define JSPAN  (N / NSPLIT)     // 512
#define TIROWS 256
#define NIT    (JSPAN / 64)     // 8 iterations (64 j each)
#define ONES16 0x3C003C00u
#define STAGES 4

#define WH_BLOCKS  (N / 16)                  // 512
#define BP_BLOCKS  (8 * (N / 8))             // 8192
#define GAT_BLOCKS (NSPLIT * (N / TIROWS))   // 512
#define NIBP       264

// ---------------- device scratch ----------------
__device__ float    g_Wh[N * OUTCH];
__device__ float    g_s1[N], g_s2[N];
__device__ unsigned g_m2u;                        // encoded float max (idempotent)
__device__ __align__(16) unsigned g_adjT[(N / 32) * N];  // bit-packed adj [word][row]
__device__ __align__(16) uint4 g_Bfrag[(N / 16) * 4 * 32];
__device__ float    g_part[NSPLIT * N * OUTCH];
__device__ float    g_Zp[NSPLIT * N];
// pipeline flags (reset by final_kernel every call)
__device__ unsigned g_whcnt;
__device__ unsigned g_tile[GAT_BLOCKS];           // [rowtile*16 + split]

__device__ __forceinline__ unsigned fenc(float f) {
    unsigned u = __float_as_uint(f);
    return (u & 0x80000000u) ? ~u : (u | 0x80000000u);
}
__device__ __forceinline__ float fdec(unsigned k) {
    return __uint_as_float((k & 0x80000000u) ? (k ^ 0x80000000u) : ~k);
}
__device__ __forceinline__ uint32_t f16x2_pack(float lo, float hi) {
    uint32_t r;
    asm("cvt.rn.f16x2.f32 %0, %1, %2;" : "=r"(r) : "f"(hi), "f"(lo));
    return r;
}
__device__ __forceinline__ uint32_t hmul2(uint32_t a, uint32_t b) {
    uint32_t d;
    asm("mul.f16x2 %0, %1, %2;" : "=r"(d) : "r"(a), "r"(b));
    return d;
}
__device__ __forceinline__ uint32_t hmax2(uint32_t a, uint32_t b) {
    uint32_t d;
    asm("max.f16x2 %0, %1, %2;" : "=r"(d) : "r"(a), "r"(b));
    return d;
}
__device__ __forceinline__ uint32_t mk_mask2(unsigned aw, int jloc) {
    const uint32_t y = (aw >> jloc) & 3u;
    const uint32_t x = y * 0x4080u;
    uint32_t m;
    asm("prmt.b32 %0, %1, %2, 0x9988;" : "=r"(m) : "r"(x), "r"(0u));
    return m;
}
__device__ __forceinline__ uint32_t smem_u32(const void* p) {
    uint32_t a;
    asm("{ .reg .u64 t; cvta.to.shared.u64 t, %1; cvt.u32.u64 %0, t; }" : "=r"(a) : "l"(p));
    return a;
}
__device__ __forceinline__ unsigned ld_acq(const unsigned* p) {
    unsigned v;
    asm volatile("ld.acquire.gpu.u32 %0, [%1];" : "=r"(v) : "l"(p) : "memory");
    return v;
}
__device__ __forceinline__ uint2 mk_ar(float s1v, float M2) {
    const float X = s1v + M2;
    const float Lrow = (X >= 0.f) ? X : 0.5f * X;
    const float A1 = expf(X - Lrow);
    const float Ah = expf(0.5f * X - Lrow);
    return make_uint2(f16x2_pack(A1, A1), f16x2_pack(Ah, Ah));
}

#define MMA16816(d, a0, a1, a2, a3, b0, b1)                                       \
    asm volatile("mma.sync.aligned.m16n8k16.row.col.f32.f16.f16.f32 "            \
        "{%0,%1,%2,%3}, {%4,%5,%6,%7}, {%8,%9}, {%0,%1,%2,%3};"                  \
        : "+f"((d)[0]), "+f"((d)[1]), "+f"((d)[2]), "+f"((d)[3])                  \
        : "r"(a0), "r"(a1), "r"(a2), "r"(a3), "r"(b0), "r"(b1))

#define CP16(dst, src) \
    asm volatile("cp.async.cg.shared.global [%0], [%1], 16;" :: "r"(dst), "l"(src) : "memory")
#define CP_COMMIT()   asm volatile("cp.async.commit_group;" ::: "memory")
#define CP_WAIT(nn)   asm volatile("cp.async.wait_group %0;" :: "n"(nn) : "memory")

// ================= merged pipeline kernel =================
// bids [0, 512): wh-GEMM + B-frag + s1/s2/max  (producer A)
// bids [512, 8704): adj bitpack               (producer B)
// bids [8704, 9216): gat mma                  (consumer, flag-gated)
__global__ __launch_bounds__(256, 2) void pipeline_kernel(const float* __restrict__ h,
                                                          const float* __restrict__ W,
                                                          const float* __restrict__ a,
                                                          const int* __restrict__ adj) {
    __shared__ __align__(16) char smraw[43008];
    const int t = threadIdx.x;
    const int bid = blockIdx.x;

    if (bid < WH_BLOCKS) {
        // ---------------- producer A: wh GEMM ----------------
        float* Ws = reinterpret_cast<float*>(smraw);
        const int col = t & 63;
        const int rowgrp = t >> 6;
        const int i0 = bid * 16;

        float acc[4] = {0.f, 0.f, 0.f, 0.f};
        for (int kc = 0; kc < 4; kc++) {
            __syncthreads();
            float4* wsv = reinterpret_cast<float4*>(Ws);
            const float4* wgv = reinterpret_cast<const float4*>(W + kc * 64 * 64);
            #pragma unroll
            for (int q = 0; q < 4; q++) wsv[t + 256 * q] = wgv[t + 256 * q];
            __syncthreads();

            #pragma unroll 4
            for (int kk = 0; kk < 64; kk += 4) {
                const int k = kc * 64 + kk;
                const float w0 = Ws[(kk + 0) * 64 + col];
                const float w1 = Ws[(kk + 1) * 64 + col];
                const float w2 = Ws[(kk + 2) * 64 + col];
                const float w3 = Ws[(kk + 3) * 64 + col];
                #pragma unroll
                for (int rr = 0; rr < 4; rr++) {
                    const int rrow = i0 + rowgrp * 4 + rr;
                    const float4 hv = *reinterpret_cast<const float4*>(h + (size_t)rrow * INCH + k);
                    acc[rr] += hv.x * w0 + hv.y * w1 + hv.z * w2 + hv.w * w3;
                }
            }
        }
        #pragma unroll
        for (int rr = 0; rr < 4; rr++)
            g_Wh[(size_t)(i0 + rowgrp * 4 + rr) * OUTCH + col] = acc[rr];

        const int kbg = i0 >> 4;
        const int nt = col >> 3;
        const int g = col & 7;
        uint32_t* bf = reinterpret_cast<uint32_t*>(g_Bfrag);
        #pragma unroll
        for (int p = 0; p < 2; p++) {
            const int kp = rowgrp * 4 + 2 * p;
            const int slotbase = (kp < 8) ? 0 : 1;
            const int tq = (kp < 8) ? (kp >> 1) : ((kp - 8) >> 1);
            const int lane = g * 4 + tq;
            const uint32_t hw = f16x2_pack(acc[2 * p], acc[2 * p + 1]);
            bf[(((size_t)(kbg * 4 + (nt >> 1)) * 32 + lane) << 2) + ((nt & 1) << 1) + slotbase] = hw;
        }

        // fused s1/s2 reduction
        const float a1c = a[col], a2c = a[64 + col];
        float p1[4], p2[4];
        #pragma unroll
        for (int rr = 0; rr < 4; rr++) { p1[rr] = acc[rr] * a1c; p2[rr] = acc[rr] * a2c; }
        #pragma unroll
        for (int o = 16; o; o >>= 1) {
            #pragma unroll
            for (int rr = 0; rr < 4; rr++) {
                p1[rr] += __shfl_xor_sync(0xffffffffu, p1[rr], o);
                p2[rr] += __shfl_xor_sync(0xffffffffu, p2[rr], o);
            }
        }
        __syncthreads();
        float* sred = reinterpret_cast<float*>(smraw);
        const int wwid = t >> 5;
        if ((t & 31) == 0) {
            #pragma unroll
            for (int rr = 0; rr < 4; rr++) {
                sred[wwid * 8 + rr] = p1[rr];
                sred[wwid * 8 + 4 + rr] = p2[rr];
            }
        }
        __syncthreads();
        if (t < 16) {
            const int rg = t >> 2, rr = t & 3;
            const float v1 = sred[(2 * rg) * 8 + rr] + sred[(2 * rg + 1) * 8 + rr];
            const float v2 = sred[(2 * rg) * 8 + 4 + rr] + sred[(2 * rg + 1) * 8 + 4 + rr];
            g_s1[i0 + rg * 4 + rr] = v1;
            g_s2[i0 + rg * 4 + rr] = v2;
            atomicMax(&g_m2u, fenc(v2));
        }
        __syncthreads();
        if (t == 0) { __threadfence(); atomicAdd(&g_whcnt, 1u); }

    } else if (bid < WH_BLOCKS + BP_BLOCKS) {
        // ---------------- producer B: adj bitpack ----------------
        unsigned* nib = reinterpret_cast<unsigned*>(smraw);   // [8][NIBP]
        const int b = bid - WH_BLOCKS;
        const int bx = b & 7;
        const int ry = b >> 3;
        const int wi = t >> 5, lane = t & 31;
        const int r = ry * 8 + wi;
        const int4* rowp = reinterpret_cast<const int4*>(adj + (size_t)r * N + (size_t)bx * 1024);
        #pragma unroll
        for (int rd = 0; rd < 8; rd++) {
            const int4 v = rowp[rd * 32 + lane];
            unsigned nb = (v.x != 0) ? 1u : 0u;
            nb |= (v.y != 0) ? 2u : 0u;
            nb |= (v.z != 0) ? 4u : 0u;
            nb |= (v.w != 0) ? 8u : 0u;
            nib[wi * NIBP + rd * 32 + lane] = nb;
        }
        __syncthreads();
        const int word = t >> 3, row = t & 7;
        const uint4 nA = *reinterpret_cast<const uint4*>(nib + row * NIBP + word * 8);
        const uint4 nB = *reinterpret_cast<const uint4*>(nib + row * NIBP + word * 8 + 4);
        unsigned wv = nA.x | (nA.y << 4) | (nA.z << 8) | (nA.w << 12)
                    | (nB.x << 16) | (nB.y << 20) | (nB.z << 24) | (nB.w << 28);
        g_adjT[(size_t)(bx * 32 + word) * N + ry * 8 + row] = wv;
        __syncthreads();
        if (t < 2) {
            __threadfence();
            atomicAdd(&g_tile[(ry >> 5) * NSPLIT + 2 * bx + t], 1u);
        }

    } else {
        // ---------------- consumer: gat mma ----------------
        uint4*    smB  = reinterpret_cast<uint4*>(smraw);                 // 32KB
        unsigned* smA  = reinterpret_cast<unsigned*>(smraw + 32768);      // 8KB
        uint2*    ephs = reinterpret_cast<uint2*>(smraw + 40960);         // 2KB

        const int bg = bid - (WH_BLOCKS + BP_BLOCKS);
        const int split = bg & (NSPLIT - 1);
        const int rowtile = bg >> 4;
        const int rowbase = rowtile * TIROWS;
        const int jbase = split * JSPAN;
        const int kbg0 = jbase >> 4;
        const int wb0 = jbase >> 5;

        // wait for producers (tid0 spins; bid order guarantees producers precede)
        if (t == 0) {
            while (ld_acq(&g_whcnt) < WH_BLOCKS) __nanosleep(128);
            const unsigned* tf = &g_tile[rowtile * NSPLIT + split];
            while (ld_acq(tf) < 32u) __nanosleep(128);
            __threadfence();
        }
        __syncthreads();

        const int w = t >> 5, lane = t & 31;
        const int g = lane >> 2, tq = lane & 3;
        const float M2 = fdec(g_m2u);

        const int r1 = rowbase + w * 32 + g;
        const int r3 = r1 + 16;
        const int rl = w * 32 + g;
        const uint2 ar1 = mk_ar(g_s1[r1], M2);
        const uint2 ar2 = mk_ar(g_s1[r1 + 8], M2);
        const uint2 ar3 = mk_ar(g_s1[r3], M2);
        const uint2 ar4 = mk_ar(g_s1[r3 + 8], M2);

        // ep segment: 256 j-pairs, one per thread
        {
            const float2 s2v = *reinterpret_cast<const float2*>(&g_s2[jbase + 2 * t]);
            const float s2a = s2v.x - M2, s2b = s2v.y - M2;
            ephs[t] = make_uint2(f16x2_pack(expf(s2a), expf(s2b)),
                                 f16x2_pack(expf(0.5f * s2a), expf(0.5f * s2b)));
        }

        float acc0[8][4], acc1[8][4];
        #pragma unroll
        for (int nt = 0; nt < 8; nt++)
            #pragma unroll
            for (int c = 0; c < 4; c++) { acc0[nt][c] = 0.f; acc1[nt][c] = 0.f; }
        float accz0[4] = {0.f, 0.f, 0.f, 0.f};
        float accz1[4] = {0.f, 0.f, 0.f, 0.f};

        const uint4* bsrc4 = g_Bfrag + (size_t)kbg0 * 128;
        const uint32_t sbB = smem_u32(smB);
        const uint32_t sbA = smem_u32(smA);
        const int aq = t >> 6;
        const int arr = (t & 63) * 4;

        #pragma unroll
        for (int s = 0; s < STAGES - 1; s++) {
            CP16(sbB + s * 8192 + t * 16, bsrc4 + (size_t)s * 512 + t);
            CP16(sbB + s * 8192 + 4096 + t * 16, bsrc4 + (size_t)s * 512 + 256 + t);
            if (t < 128)
                CP16(sbA + s * 2048 + aq * 1024 + arr * 4,
                     g_adjT + (size_t)(wb0 + 2 * s + aq) * N + rowbase + arr);
            CP_COMMIT();
        }

        for (int hh = 0; hh < NIT; hh++) {
            const int slot = hh % STAGES;
            CP_WAIT(2);
            __syncthreads();

            if (hh + STAGES - 1 < NIT) {
                const int hs = hh + STAGES - 1;
                const int ns = hs % STAGES;
                CP16(sbB + ns * 8192 + t * 16, bsrc4 + (size_t)hs * 512 + t);
                CP16(sbB + ns * 8192 + 4096 + t * 16, bsrc4 + (size_t)hs * 512 + 256 + t);
                if (t < 128)
                    CP16(sbA + ns * 2048 + aq * 1024 + arr * 4,
                         g_adjT + (size_t)(wb0 + 2 * hs + aq) * N + rowbase + arr);
            }
            CP_COMMIT();

            const uint4* bs = smB + slot * 512;
            const uint2* es = ephs + hh * 32;
            const unsigned* as = smA + slot * 512;

            unsigned cw[2][4];
            #pragma unroll
            for (int q = 0; q < 2; q++) {
                cw[q][0] = as[q * 256 + rl];
                cw[q][1] = as[q * 256 + rl + 8];
                cw[q][2] = as[q * 256 + rl + 16];
                cw[q][3] = as[q * 256 + rl + 24];
            }

            #pragma unroll
            for (int q = 0; q < 2; q++) {
                #pragma unroll
                for (int kb = 0; kb < 2; kb++) {
                    const int kt = q * 2 + kb;
                    uint32_t av0[4], av1[4];
                    #pragma unroll
                    for (int pr = 0; pr < 2; pr++) {
                        const int jloc = kb * 16 + pr * 8 + 2 * tq;
                        const uint2 e = es[kt * 8 + pr * 4 + tq];
                        const uint32_t e1h = hmul2(ar1.x, e.x), e1l = hmul2(ar1.y, e.y);
                        const uint32_t e2h = hmul2(ar2.x, e.x), e2l = hmul2(ar2.y, e.y);
                        const uint32_t e3h = hmul2(ar3.x, e.x), e3l = hmul2(ar3.y, e.y);
                        const uint32_t e4h = hmul2(ar4.x, e.x), e4l = hmul2(ar4.y, e.y);
                        av0[2 * pr + 0] = hmax2(e1h, e1l) & mk_mask2(cw[q][0], jloc);
                        av0[2 * pr + 1] = hmax2(e2h, e2l) & mk_mask2(cw[q][1], jloc);
                        av1[2 * pr + 0] = hmax2(e3h, e3l) & mk_mask2(cw[q][2], jloc);
                        av1[2 * pr + 1] = hmax2(e4h, e4l) & mk_mask2(cw[q][3], jloc);
                    }
                    #pragma unroll
                    for (int ntp = 0; ntp < 4; ntp++) {
                        const uint4 b = bs[(kt * 4 + ntp) * 32 + lane];
                        MMA16816(acc0[2 * ntp + 0], av0[0], av0[1], av0[2], av0[3], b.x, b.y);
                        MMA16816(acc0[2 * ntp + 1], av0[0], av0[1], av0[2], av0[3], b.z, b.w);
                        MMA16816(acc1[2 * ntp + 0], av1[0], av1[1], av1[2], av1[3], b.x, b.y);
                        MMA16816(acc1[2 * ntp + 1], av1[0], av1[1], av1[2], av1[3], b.z, b.w);
                    }
                    MMA16816(accz0, av0[0], av0[1], av0[2], av0[3], ONES16, ONES16);
                    MMA16816(accz1, av1[0], av1[1], av1[2], av1[3], ONES16, ONES16);
                }
            }
        }

        if (tq == 0) {
            g_Zp[split * N + r1]     = accz0[0];
            g_Zp[split * N + r1 + 8] = accz0[2];
            g_Zp[split * N + r3]     = accz1[0];
            g_Zp[split * N + r3 + 8] = accz1[2];
        }

        float* p1 = g_part + ((size_t)split * N + r1) * 64;
        float* p2 = g_part + ((size_t)split * N + r1 + 8) * 64;
        float* p3 = g_part + ((size_t)split * N + r3) * 64;
        float* p4 = g_part + ((size_t)split * N + r3 + 8) * 64;
        #pragma unroll
        for (int nt = 0; nt < 8; nt++) {
            const int c = nt * 8 + 2 * tq;
            *reinterpret_cast<float2*>(p1 + c) = make_float2(acc0[nt][0], acc0[nt][1]);
            *reinterpret_cast<float2*>(p2 + c) = make_float2(acc0[nt][2], acc0[nt][3]);
            *reinterpret_cast<float2*>(p3 + c) = make_float2(acc1[nt][0], acc1[nt][1]);
            *reinterpret_cast<float2*>(p4 + c) = make_float2(acc1[nt][2], acc1[nt][3]);
        }
    }
}

// ================= final: combine splits, normalize, relu, reset flags =========
__global__ __launch_bounds__(256) void final_kernel(float* __restrict__ out) {
    // reset pipeline flags for the next graph replay
    if (blockIdx.x == 0) {
        if (threadIdx.x < GAT_BLOCKS) g_tile[threadIdx.x] = 0;   // 256 < 512: two rounds
        if (threadIdx.x + 256 < GAT_BLOCKS) g_tile[threadIdx.x + 256] = 0;
        if (threadIdx.x == 0) g_whcnt = 0;
    }

    const int idx = blockIdx.x * 256 + threadIdx.x;   // 8192*16 float4s
    const int row = idx >> 4;
    const int c4 = idx & 15;
    float z = 0.f;
    #pragma unroll
    for (int sp = 0; sp < NSPLIT; sp++) z += g_Zp[sp * N + row];
    const float inv = 1.f / z;
    const size_t off = (size_t)row * 64 + c4 * 4;
    float4 s = *reinterpret_cast<const float4*>(g_part + off);
    #pragma unroll
    for (int sp = 1; sp < NSPLIT; sp++) {
        const float4 p = *reinterpret_cast<const float4*>(g_part + (size_t)sp * N * 64 + off);
        s.x += p.x; s.y += p.y; s.z += p.z; s.w += p.w;
    }
    *reinterpret_cast<float4*>(out + off) = make_float4(
        fmaxf(s.x * inv, 0.f), fmaxf(s.y * inv, 0.f),
        fmaxf(s.z * inv, 0.f), fmaxf(s.w * inv, 0.f));
}

// ================= launch =================
extern "C" void kernel_launch(void* const* d_in, const int* in_sizes, int n_in,
                              void* d_out, int out_size) {
    const float* h   = (const float*)d_in[0];
    const int*   adj = (const int*)d_in[1];
    const float* W   = (const float*)d_in[2];
    const float* a   = (const float*)d_in[3];
    float*       out = (float*)d_out;

    pipeline_kernel<<<WH_BLOCKS + BP_BLOCKS + GAT_BLOCKS, 256>>>(h, W, a, adj);
    final_kernel<<<(N * 16) / 256, 256>>>(out);
}